// round 9
// baseline (speedup 1.0000x reference)
#include <cuda_runtime.h>
#include <cuda_bf16.h>
#include <cstdint>
#include <math.h>

#define NB 8192
#define ND 128
#define C_ALPHA 2.0f
#define C_BETA 50.0f
#define C_BASE 0.5f
#define C_MARGIN 0.1f

// ---------------------------------------------------------------------------
// Scratch (allocation-free rule: __device__ globals)
// ---------------------------------------------------------------------------
__device__ float g_sim[(size_t)NB * NB];           // upper-triangle tiles only
__device__ __nv_bfloat16 g_Ehi[(size_t)NB * ND];
__device__ __nv_bfloat16 g_Elo[(size_t)NB * ND];
__device__ float g_pmin[NB], g_nmax[NB], g_psum[NB], g_nsum[NB];

__device__ __forceinline__ uint32_t smem_u32(const void* p) {
    uint32_t a;
    asm("{ .reg .u64 t; cvta.to.shared.u64 t, %1; cvt.u32.u64 %0, t; }" : "=r"(a) : "l"(p));
    return a;
}

#define LDMATRIX_X4(r0, r1, r2, r3, addr)                                      \
    asm volatile("ldmatrix.sync.aligned.m8n8.x4.shared.b16 {%0,%1,%2,%3}, [%4];" \
                 : "=r"(r0), "=r"(r1), "=r"(r2), "=r"(r3) : "r"(addr))
#define LDMATRIX_X2(r0, r1, addr)                                              \
    asm volatile("ldmatrix.sync.aligned.m8n8.x2.shared.b16 {%0,%1}, [%2];"     \
                 : "=r"(r0), "=r"(r1) : "r"(addr))
#define MMA16816(c, a, b)                                                      \
    asm volatile("mma.sync.aligned.m16n8k16.row.col.f32.bf16.bf16.f32 "        \
                 "{%0,%1,%2,%3}, {%4,%5,%6,%7}, {%8,%9}, {%0,%1,%2,%3};"       \
                 : "+f"((c)[0]), "+f"((c)[1]), "+f"((c)[2]), "+f"((c)[3])      \
                 : "r"((a)[0]), "r"((a)[1]), "r"((a)[2]), "r"((a)[3]),         \
                   "r"((b)[0]), "r"((b)[1]))
#define CP_ASYNC16(sa, gp)                                                     \
    asm volatile("cp.async.cg.shared.global [%0], [%1], 16;" :: "r"(sa), "l"(gp))
#define CP_COMMIT() asm volatile("cp.async.commit_group;")
#define CP_WAIT(n)  asm volatile("cp.async.wait_group %0;" :: "n"(n))

// order-preserving float atomics
__device__ __forceinline__ void atomicMinF(float* a, float v) {
    if (v >= 0.0f) atomicMin((int*)a, __float_as_int(v));
    else           atomicMax((unsigned*)a, __float_as_uint(v));
}
__device__ __forceinline__ void atomicMaxF(float* a, float v) {
    if (v >= 0.0f) atomicMax((int*)a, __float_as_int(v));
    else           atomicMin((unsigned*)a, __float_as_uint(v));
}

__device__ __forceinline__ void tri_decode(int t, int& by, int& bx) {
    int rem = t, y = 0;
    while (rem >= (NB / 128) - y) { rem -= (NB / 128) - y; y++; }
    by = y; bx = y + rem;
}

#define NTILE (NB / 128)
#define NTRI (NTILE * (NTILE + 1) / 2)    // 2080
#define TLE 129                           // fp32 tile stride: (r+l)%32 banks

// ---------------------------------------------------------------------------
// Kernel 0: split fp32 -> bf16 hi/lo, init per-row accumulators
// ---------------------------------------------------------------------------
__global__ __launch_bounds__(256) void split_kernel(const float* __restrict__ E) {
    int i = blockIdx.x * 256 + threadIdx.x;
    if (i < NB) {
        g_pmin[i] = INFINITY;  g_nmax[i] = -INFINITY;
        g_psum[i] = 0.0f;      g_nsum[i] = 0.0f;
    }
    float x = E[i];
    __nv_bfloat16 h = __float2bfloat16(x);
    g_Ehi[i] = h;
    g_Elo[i] = __float2bfloat16(x - __bfloat162float(h));
}

// ---------------------------------------------------------------------------
// Kernel 1: upper-triangle GEMM (cp.async pipeline) + FUSED extrema scans.
// After MMA, tile staged to SMEM; warp-per-line masked min/max in both
// orientations folds into g_pmin/g_nmax (no extra DRAM pass).
// ---------------------------------------------------------------------------
#define PAD 8
#define LDT (ND + PAD)
#define ROWB (LDT * 2)
#define OFF_AHI 0
#define OFF_ALO (OFF_AHI + 128 * ROWB)
#define OFF_BHI (OFF_ALO + 128 * ROWB)
#define OFF_BLO (OFF_BHI + 128 * ROWB)
#define GEMM_SMEM (OFF_BLO + 128 * ROWB)  // 139264 (>= 128*TLE*4 = 66048)

__device__ __forceinline__ void gemm_pass(float (&acc)[4][4][4], uint32_t Ab, uint32_t Bb,
                                          int mbase, int nbase, int arow, int acol,
                                          int brow, int bcol) {
#pragma unroll
    for (int k0 = 0; k0 < ND; k0 += 16) {
        uint32_t a[4][4], b[4][2];
#pragma unroll
        for (int mi = 0; mi < 4; mi++) {
            uint32_t ad = Ab + ((mbase + mi * 16 + arow) * LDT + k0 + acol) * 2;
            LDMATRIX_X4(a[mi][0], a[mi][1], a[mi][2], a[mi][3], ad);
        }
#pragma unroll
        for (int ni = 0; ni < 4; ni++) {
            uint32_t bd = Bb + ((nbase + ni * 8 + brow) * LDT + k0 + bcol) * 2;
            LDMATRIX_X2(b[ni][0], b[ni][1], bd);
        }
#pragma unroll
        for (int mi = 0; mi < 4; mi++)
#pragma unroll
            for (int ni = 0; ni < 4; ni++)
                MMA16816(acc[mi][ni], a[mi], b[ni]);
    }
}

__global__ __launch_bounds__(256, 1) void gemm_mma_kernel(const int* __restrict__ labels) {
    int by, bx;
    tri_decode(blockIdx.x, by, bx);

    extern __shared__ char smem[];
    __shared__ int labA[128], labB[128];
    const uint32_t sbase = smem_u32(smem);
    const int tid  = threadIdx.x;
    const int wid  = tid >> 5;
    const int lane = tid & 31;
    const int bm = by * 128;
    const int bn = bx * 128;
    const bool diag = (bx == by);

    if (tid < 128) labA[tid] = labels[bm + tid];
    else           labB[tid - 128] = labels[bn + tid - 128];

    for (int t = tid; t < 2048; t += 256) {
        const int r = t >> 4;
        const int c = t & 15;
        const uint32_t so = (uint32_t)r * ROWB + c * 16;
        CP_ASYNC16(sbase + OFF_AHI + so, (const char*)(g_Ehi + (size_t)(bm + r) * ND) + c * 16);
        if (!diag)
            CP_ASYNC16(sbase + OFF_BHI + so, (const char*)(g_Ehi + (size_t)(bn + r) * ND) + c * 16);
    }
    CP_COMMIT();
    for (int t = tid; t < 2048; t += 256) {
        const int r = t >> 4;
        const int c = t & 15;
        const uint32_t so = (uint32_t)r * ROWB + c * 16;
        CP_ASYNC16(sbase + OFF_ALO + so, (const char*)(g_Elo + (size_t)(bm + r) * ND) + c * 16);
        if (!diag)
            CP_ASYNC16(sbase + OFF_BLO + so, (const char*)(g_Elo + (size_t)(bn + r) * ND) + c * 16);
    }
    CP_COMMIT();

    const int warp_m = wid >> 2;
    const int warp_n = wid & 3;
    const int mbase = warp_m * 64;
    const int nbase = warp_n * 32;
    const int arow = ((lane >> 3) & 1) * 8 + (lane & 7);
    const int acol = ((lane >> 4) & 1) * 8;
    const int brow = lane & 7;
    const int bcol = ((lane >> 3) & 1) * 8;

    float acc[4][4][4];
#pragma unroll
    for (int mi = 0; mi < 4; mi++)
#pragma unroll
        for (int ni = 0; ni < 4; ni++)
#pragma unroll
            for (int q = 0; q < 4; q++) acc[mi][ni][q] = 0.0f;

    const uint32_t aHi = sbase + OFF_AHI;
    const uint32_t aLo = sbase + OFF_ALO;
    const uint32_t bHi = diag ? aHi : sbase + OFF_BHI;
    const uint32_t bLo = diag ? aLo : sbase + OFF_BLO;

    CP_WAIT(1);
    __syncthreads();
    gemm_pass(acc, aHi, bHi, mbase, nbase, arow, acol, brow, bcol);   // hi*hi
    CP_WAIT(0);
    __syncthreads();
    gemm_pass(acc, aHi, bLo, mbase, nbase, arow, acol, brow, bcol);   // hi*lo
    gemm_pass(acc, aLo, bHi, mbase, nbase, arow, acol, brow, bcol);   // lo*hi

    // ---- direct gmem store (upper-triangle tile) ----
    const int g   = lane >> 2;
    const int tig = lane & 3;
#pragma unroll
    for (int mi = 0; mi < 4; mi++) {
        const size_t row0 = (size_t)(bm + mbase + mi * 16 + g);
        const size_t row1 = row0 + 8;
#pragma unroll
        for (int ni = 0; ni < 4; ni++) {
            const int col = bn + nbase + ni * 8 + tig * 2;
            *(float2*)(g_sim + row0 * NB + col) = make_float2(acc[mi][ni][0], acc[mi][ni][1]);
            *(float2*)(g_sim + row1 * NB + col) = make_float2(acc[mi][ni][2], acc[mi][ni][3]);
        }
    }

    // ---- stage tile into SMEM for fused extrema ----
    __syncthreads();                       // bf16 operand reads done
    float* st = (float*)smem;              // [128][TLE]
#pragma unroll
    for (int mi = 0; mi < 4; mi++) {
        const int r0 = mbase + mi * 16 + g;
#pragma unroll
        for (int ni = 0; ni < 4; ni++) {
            const int c0 = nbase + ni * 8 + tig * 2;
            st[r0 * TLE + c0]           = acc[mi][ni][0];
            st[r0 * TLE + c0 + 1]       = acc[mi][ni][1];
            st[(r0 + 8) * TLE + c0]     = acc[mi][ni][2];
            st[(r0 + 8) * TLE + c0 + 1] = acc[mi][ni][3];
        }
    }
    __syncthreads();

    // ---- warp-per-line extrema: rows (i = bm+r, cols masked by labB) ----
    for (int k = 0; k < 16; k++) {
        const int r  = wid * 16 + k;
        const int li = labA[r];
        float pmin = INFINITY, nmax = -INFINITY;
#pragma unroll
        for (int q = 0; q < 4; q++) {
            const int c = lane + 32 * q;
            if (diag && c == r) continue;
            const float s = st[r * TLE + c];
            if (labB[c] == li) pmin = fminf(pmin, s);
            else               nmax = fmaxf(nmax, s);
        }
#pragma unroll
        for (int o = 16; o; o >>= 1) {
            pmin = fminf(pmin, __shfl_xor_sync(0xFFFFFFFFu, pmin, o));
            nmax = fmaxf(nmax, __shfl_xor_sync(0xFFFFFFFFu, nmax, o));
        }
        if (lane == 0) {
            if (pmin < INFINITY)  atomicMinF(&g_pmin[bm + r], pmin);
            if (nmax > -INFINITY) atomicMaxF(&g_nmax[bm + r], nmax);
        }
    }
    // ---- cols (i = bn+c, rows masked by labA); skip on diagonal ----
    if (!diag) {
        for (int k = 0; k < 16; k++) {
            const int c  = wid * 16 + k;
            const int li = labB[c];
            float pmin = INFINITY, nmax = -INFINITY;
#pragma unroll
            for (int q = 0; q < 4; q++) {
                const int r = lane + 32 * q;
                const float s = st[r * TLE + c];
                if (labA[r] == li) pmin = fminf(pmin, s);
                else               nmax = fmaxf(nmax, s);
            }
#pragma unroll
            for (int o = 16; o; o >>= 1) {
                pmin = fminf(pmin, __shfl_xor_sync(0xFFFFFFFFu, pmin, o));
                nmax = fmaxf(nmax, __shfl_xor_sync(0xFFFFFFFFu, nmax, o));
            }
            if (lane == 0) {
                if (pmin < INFINITY)  atomicMinF(&g_pmin[bn + c], pmin);
                if (nmax > -INFINITY) atomicMaxF(&g_nmax[bn + c], nmax);
            }
        }
    }
}

// ---------------------------------------------------------------------------
// Kernel 2: hard-pair exp sums, warp-per-line over staged tile
// ---------------------------------------------------------------------------
#define TILE_SMEM (128 * TLE * 4)         // 66048

__global__ __launch_bounds__(256) void sum_kernel(const int* __restrict__ labels) {
    extern __shared__ float st[];
    __shared__ int labA[128], labB[128];
    int by, bx;
    tri_decode(blockIdx.x, by, bx);
    const int bm = by * 128, bn = bx * 128;
    const bool diag = (bx == by);
    const int tid  = threadIdx.x;
    const int wid  = tid >> 5;
    const int lane = tid & 31;

    if (tid < 128) labA[tid] = labels[bm + tid];
    else           labB[tid - 128] = labels[bn + tid - 128];

    for (int t = tid; t < 128 * 32; t += 256) {
        const int r = t >> 5, c4 = (t & 31) * 4;
        float4 v = *(const float4*)(g_sim + (size_t)(bm + r) * NB + bn + c4);
        st[r * TLE + c4 + 0] = v.x; st[r * TLE + c4 + 1] = v.y;
        st[r * TLE + c4 + 2] = v.z; st[r * TLE + c4 + 3] = v.w;
    }
    __syncthreads();

    // rows: i = bm+r
    for (int k = 0; k < 16; k++) {
        const int r  = wid * 16 + k;
        const int i  = bm + r;
        const int li = labA[r];
        const float pmin = g_pmin[i], nmax = g_nmax[i];
        const float nthr = nmax - 0.45f;   // skipped terms < e^-22.5 * max term
        float psum = 0.0f, nsum = 0.0f;
#pragma unroll
        for (int q = 0; q < 4; q++) {
            const int c = lane + 32 * q;
            if (diag && c == r) continue;
            const float s = st[r * TLE + c];
            if (labB[c] == li) {
                if (s - C_MARGIN < nmax) psum += __expf(-C_ALPHA * (s - C_BASE));
            } else {
                if (s + C_MARGIN > pmin && s > nthr) nsum += __expf(C_BETA * (s - C_BASE));
            }
        }
#pragma unroll
        for (int o = 16; o; o >>= 1) {
            psum += __shfl_xor_sync(0xFFFFFFFFu, psum, o);
            nsum += __shfl_xor_sync(0xFFFFFFFFu, nsum, o);
        }
        if (lane == 0) {
            if (psum > 0.0f) atomicAdd(&g_psum[i], psum);
            if (nsum > 0.0f) atomicAdd(&g_nsum[i], nsum);
        }
    }
    // cols: i = bn+c (mirror), skip on diagonal
    if (!diag) {
        for (int k = 0; k < 16; k++) {
            const int c  = wid * 16 + k;
            const int i  = bn + c;
            const int li = labB[c];
            const float pmin = g_pmin[i], nmax = g_nmax[i];
            const float nthr = nmax - 0.45f;
            float psum = 0.0f, nsum = 0.0f;
#pragma unroll
            for (int q = 0; q < 4; q++) {
                const int r = lane + 32 * q;
                const float s = st[r * TLE + c];
                if (labA[r] == li) {
                    if (s - C_MARGIN < nmax) psum += __expf(-C_ALPHA * (s - C_BASE));
                } else {
                    if (s + C_MARGIN > pmin && s > nthr) nsum += __expf(C_BETA * (s - C_BASE));
                }
            }
#pragma unroll
            for (int o = 16; o; o >>= 1) {
                psum += __shfl_xor_sync(0xFFFFFFFFu, psum, o);
                nsum += __shfl_xor_sync(0xFFFFFFFFu, nsum, o);
            }
            if (lane == 0) {
                if (psum > 0.0f) atomicAdd(&g_psum[i], psum);
                if (nsum > 0.0f) atomicAdd(&g_nsum[i], nsum);
            }
        }
    }
}

// ---------------------------------------------------------------------------
// Kernel 3: finalize (one CTA)
// ---------------------------------------------------------------------------
__global__ __launch_bounds__(1024) void final_kernel(float* __restrict__ out) {
    __shared__ float sbuf[32];
    __shared__ int   scnt[32];
    const int tid = threadIdx.x;
    float ls = 0.0f; int nv = 0;
    for (int i = tid; i < NB; i += 1024) {
        const float pmin = g_pmin[i], nmax = g_nmax[i];
        const float ps = g_psum[i], ns = g_nsum[i];
        if (pmin < INFINITY && nmax > -INFINITY && ps > 0.0f && ns > 0.0f) {
            ls += log1pf(ps) / C_ALPHA + log1pf(ns) / C_BETA;
            nv++;
        }
    }
#pragma unroll
    for (int o = 16; o; o >>= 1) {
        ls += __shfl_xor_sync(0xFFFFFFFFu, ls, o);
        nv += __shfl_xor_sync(0xFFFFFFFFu, nv, o);
    }
    if ((tid & 31) == 0) { sbuf[tid >> 5] = ls; scnt[tid >> 5] = nv; }
    __syncthreads();
    if (tid == 0) {
        float s = 0.0f; int n = 0;
#pragma unroll
        for (int k = 0; k < 32; k++) { s += sbuf[k]; n += scnt[k]; }
        out[0] = s / (float)(n > 1 ? n : 1);
    }
}

// ---------------------------------------------------------------------------
extern "C" void kernel_launch(void* const* d_in, const int* in_sizes, int n_in,
                              void* d_out, int out_size) {
    const float* E      = (const float*)d_in[0];
    const int*   labels = (const int*)d_in[1];
    float*       out    = (float*)d_out;

    cudaFuncSetAttribute(gemm_mma_kernel, cudaFuncAttributeMaxDynamicSharedMemorySize,
                         GEMM_SMEM);
    cudaFuncSetAttribute(sum_kernel, cudaFuncAttributeMaxDynamicSharedMemorySize,
                         TILE_SMEM);

    split_kernel<<<NB * ND / 256, 256>>>(E);
    gemm_mma_kernel<<<NTRI, 256, GEMM_SMEM>>>(labels);
    sum_kernel<<<NTRI, 256, TILE_SMEM>>>(labels);
    final_kernel<<<1, 1024>>>(out);
}

// round 10
// speedup vs baseline: 1.1347x; 1.1347x over previous
#include <cuda_runtime.h>
#include <cuda_bf16.h>
#include <cstdint>
#include <math.h>

#define NB 8192
#define ND 128
#define C_ALPHA 2.0f
#define C_BETA 50.0f
#define C_BASE 0.5f
#define C_MARGIN 0.1f

// ---------------------------------------------------------------------------
// Scratch (allocation-free rule: __device__ globals)
// ---------------------------------------------------------------------------
__device__ float g_sim[(size_t)NB * NB];           // upper-triangle tiles only
__device__ __nv_bfloat16 g_Ehi[(size_t)NB * ND];
__device__ __nv_bfloat16 g_Elo[(size_t)NB * ND];
__device__ float g_pmin[NB], g_nmax[NB], g_psum[NB], g_nsum[NB];

__device__ __forceinline__ uint32_t smem_u32(const void* p) {
    uint32_t a;
    asm("{ .reg .u64 t; cvta.to.shared.u64 t, %1; cvt.u32.u64 %0, t; }" : "=r"(a) : "l"(p));
    return a;
}

#define LDMATRIX_X4(r0, r1, r2, r3, addr)                                      \
    asm volatile("ldmatrix.sync.aligned.m8n8.x4.shared.b16 {%0,%1,%2,%3}, [%4];" \
                 : "=r"(r0), "=r"(r1), "=r"(r2), "=r"(r3) : "r"(addr))
#define LDMATRIX_X2(r0, r1, addr)                                              \
    asm volatile("ldmatrix.sync.aligned.m8n8.x2.shared.b16 {%0,%1}, [%2];"     \
                 : "=r"(r0), "=r"(r1) : "r"(addr))
#define MMA16816(c, a, b)                                                      \
    asm volatile("mma.sync.aligned.m16n8k16.row.col.f32.bf16.bf16.f32 "        \
                 "{%0,%1,%2,%3}, {%4,%5,%6,%7}, {%8,%9}, {%0,%1,%2,%3};"       \
                 : "+f"((c)[0]), "+f"((c)[1]), "+f"((c)[2]), "+f"((c)[3])      \
                 : "r"((a)[0]), "r"((a)[1]), "r"((a)[2]), "r"((a)[3]),         \
                   "r"((b)[0]), "r"((b)[1]))
#define CP_ASYNC16(sa, gp)                                                     \
    asm volatile("cp.async.cg.shared.global [%0], [%1], 16;" :: "r"(sa), "l"(gp))
#define CP_COMMIT() asm volatile("cp.async.commit_group;")
#define CP_WAIT(n)  asm volatile("cp.async.wait_group %0;" :: "n"(n))

// order-preserving float atomics
__device__ __forceinline__ void atomicMinF(float* a, float v) {
    if (v >= 0.0f) atomicMin((int*)a, __float_as_int(v));
    else           atomicMax((unsigned*)a, __float_as_uint(v));
}
__device__ __forceinline__ void atomicMaxF(float* a, float v) {
    if (v >= 0.0f) atomicMax((int*)a, __float_as_int(v));
    else           atomicMin((unsigned*)a, __float_as_uint(v));
}

__device__ __forceinline__ void tri_decode(int t, int& by, int& bx) {
    int rem = t, y = 0;
    while (rem >= (NB / 128) - y) { rem -= (NB / 128) - y; y++; }
    by = y; bx = y + rem;
}

#define NTILE (NB / 128)
#define NTRI (NTILE * (NTILE + 1) / 2)    // 2080
#define TLE 129                           // fp32 tile stride: conflict-free both ways

// ---------------------------------------------------------------------------
// Kernel 0: split fp32 -> bf16 hi/lo, init per-row accumulators
// ---------------------------------------------------------------------------
__global__ __launch_bounds__(256) void split_kernel(const float* __restrict__ E) {
    int i = blockIdx.x * 256 + threadIdx.x;
    if (i < NB) {
        g_pmin[i] = INFINITY;  g_nmax[i] = -INFINITY;
        g_psum[i] = 0.0f;      g_nsum[i] = 0.0f;
    }
    float x = E[i];
    __nv_bfloat16 h = __float2bfloat16(x);
    g_Ehi[i] = h;
    g_Elo[i] = __float2bfloat16(x - __bfloat162float(h));
}

// ---------------------------------------------------------------------------
// Kernel 1: upper-triangle GEMM via mma.sync, cp.async pipeline (round-8 lean)
// ---------------------------------------------------------------------------
#define PAD 8
#define LDT (ND + PAD)
#define ROWB (LDT * 2)
#define OFF_AHI 0
#define OFF_ALO (OFF_AHI + 128 * ROWB)
#define OFF_BHI (OFF_ALO + 128 * ROWB)
#define OFF_BLO (OFF_BHI + 128 * ROWB)
#define GEMM_SMEM (OFF_BLO + 128 * ROWB)  // 139264

__device__ __forceinline__ void gemm_pass(float (&acc)[4][4][4], uint32_t Ab, uint32_t Bb,
                                          int mbase, int nbase, int arow, int acol,
                                          int brow, int bcol) {
#pragma unroll
    for (int k0 = 0; k0 < ND; k0 += 16) {
        uint32_t a[4][4], b[4][2];
#pragma unroll
        for (int mi = 0; mi < 4; mi++) {
            uint32_t ad = Ab + ((mbase + mi * 16 + arow) * LDT + k0 + acol) * 2;
            LDMATRIX_X4(a[mi][0], a[mi][1], a[mi][2], a[mi][3], ad);
        }
#pragma unroll
        for (int ni = 0; ni < 4; ni++) {
            uint32_t bd = Bb + ((nbase + ni * 8 + brow) * LDT + k0 + bcol) * 2;
            LDMATRIX_X2(b[ni][0], b[ni][1], bd);
        }
#pragma unroll
        for (int mi = 0; mi < 4; mi++)
#pragma unroll
            for (int ni = 0; ni < 4; ni++)
                MMA16816(acc[mi][ni], a[mi], b[ni]);
    }
}

__global__ __launch_bounds__(256, 1) void gemm_mma_kernel() {
    int by, bx;
    tri_decode(blockIdx.x, by, bx);

    extern __shared__ char smem[];
    const uint32_t sbase = smem_u32(smem);
    const int tid  = threadIdx.x;
    const int wid  = tid >> 5;
    const int lane = tid & 31;
    const int bm = by * 128;
    const int bn = bx * 128;
    const bool diag = (bx == by);

    for (int t = tid; t < 2048; t += 256) {
        const int r = t >> 4;
        const int c = t & 15;
        const uint32_t so = (uint32_t)r * ROWB + c * 16;
        CP_ASYNC16(sbase + OFF_AHI + so, (const char*)(g_Ehi + (size_t)(bm + r) * ND) + c * 16);
        if (!diag)
            CP_ASYNC16(sbase + OFF_BHI + so, (const char*)(g_Ehi + (size_t)(bn + r) * ND) + c * 16);
    }
    CP_COMMIT();
    for (int t = tid; t < 2048; t += 256) {
        const int r = t >> 4;
        const int c = t & 15;
        const uint32_t so = (uint32_t)r * ROWB + c * 16;
        CP_ASYNC16(sbase + OFF_ALO + so, (const char*)(g_Elo + (size_t)(bm + r) * ND) + c * 16);
        if (!diag)
            CP_ASYNC16(sbase + OFF_BLO + so, (const char*)(g_Elo + (size_t)(bn + r) * ND) + c * 16);
    }
    CP_COMMIT();

    const int warp_m = wid >> 2;
    const int warp_n = wid & 3;
    const int mbase = warp_m * 64;
    const int nbase = warp_n * 32;
    const int arow = ((lane >> 3) & 1) * 8 + (lane & 7);
    const int acol = ((lane >> 4) & 1) * 8;
    const int brow = lane & 7;
    const int bcol = ((lane >> 3) & 1) * 8;

    float acc[4][4][4];
#pragma unroll
    for (int mi = 0; mi < 4; mi++)
#pragma unroll
        for (int ni = 0; ni < 4; ni++)
#pragma unroll
            for (int q = 0; q < 4; q++) acc[mi][ni][q] = 0.0f;

    const uint32_t aHi = sbase + OFF_AHI;
    const uint32_t aLo = sbase + OFF_ALO;
    const uint32_t bHi = diag ? aHi : sbase + OFF_BHI;
    const uint32_t bLo = diag ? aLo : sbase + OFF_BLO;

    CP_WAIT(1);
    __syncthreads();
    gemm_pass(acc, aHi, bHi, mbase, nbase, arow, acol, brow, bcol);   // hi*hi
    CP_WAIT(0);
    __syncthreads();
    gemm_pass(acc, aHi, bLo, mbase, nbase, arow, acol, brow, bcol);   // hi*lo
    gemm_pass(acc, aLo, bHi, mbase, nbase, arow, acol, brow, bcol);   // lo*hi

    const int g   = lane >> 2;
    const int tig = lane & 3;
#pragma unroll
    for (int mi = 0; mi < 4; mi++) {
        const size_t row0 = (size_t)(bm + mbase + mi * 16 + g);
        const size_t row1 = row0 + 8;
#pragma unroll
        for (int ni = 0; ni < 4; ni++) {
            const int col = bn + nbase + ni * 8 + tig * 2;
            *(float2*)(g_sim + row0 * NB + col) = make_float2(acc[mi][ni][0], acc[mi][ni][1]);
            *(float2*)(g_sim + row1 * NB + col) = make_float2(acc[mi][ni][2], acc[mi][ni][3]);
        }
    }
}

// ---------------------------------------------------------------------------
// Kernel 2: extrema, warp-per-line over staged tile (both orientations)
// ---------------------------------------------------------------------------
#define TILE_SMEM (128 * TLE * 4)         // 66048

__global__ __launch_bounds__(256) void extrema_kernel(const int* __restrict__ labels) {
    extern __shared__ float st[];
    __shared__ int labA[128], labB[128];
    int by, bx;
    tri_decode(blockIdx.x, by, bx);
    const int bm = by * 128, bn = bx * 128;
    const bool diag = (bx == by);
    const int tid  = threadIdx.x;
    const int wid  = tid >> 5;
    const int lane = tid & 31;

    if (tid < 128) labA[tid] = labels[bm + tid];
    else           labB[tid - 128] = labels[bn + tid - 128];

    for (int t = tid; t < 128 * 32; t += 256) {
        const int r = t >> 5, c4 = (t & 31) * 4;
        float4 v = *(const float4*)(g_sim + (size_t)(bm + r) * NB + bn + c4);
        st[r * TLE + c4 + 0] = v.x; st[r * TLE + c4 + 1] = v.y;
        st[r * TLE + c4 + 2] = v.z; st[r * TLE + c4 + 3] = v.w;
    }
    __syncthreads();

    // rows: i = bm+r, cols masked by labB
    for (int k = 0; k < 16; k++) {
        const int r  = wid * 16 + k;
        const int li = labA[r];
        float pmin = INFINITY, nmax = -INFINITY;
#pragma unroll
        for (int q = 0; q < 4; q++) {
            const int c = lane + 32 * q;
            if (diag && c == r) continue;
            const float s = st[r * TLE + c];
            if (labB[c] == li) pmin = fminf(pmin, s);
            else               nmax = fmaxf(nmax, s);
        }
#pragma unroll
        for (int o = 16; o; o >>= 1) {
            pmin = fminf(pmin, __shfl_xor_sync(0xFFFFFFFFu, pmin, o));
            nmax = fmaxf(nmax, __shfl_xor_sync(0xFFFFFFFFu, nmax, o));
        }
        if (lane == 0) {
            if (pmin < INFINITY)  atomicMinF(&g_pmin[bm + r], pmin);
            if (nmax > -INFINITY) atomicMaxF(&g_nmax[bm + r], nmax);
        }
    }
    // cols: i = bn+c, rows masked by labA (skip on diagonal)
    if (!diag) {
        for (int k = 0; k < 16; k++) {
            const int c  = wid * 16 + k;
            const int li = labB[c];
            float pmin = INFINITY, nmax = -INFINITY;
#pragma unroll
            for (int q = 0; q < 4; q++) {
                const int r = lane + 32 * q;
                const float s = st[r * TLE + c];
                if (labA[r] == li) pmin = fminf(pmin, s);
                else               nmax = fmaxf(nmax, s);
            }
#pragma unroll
            for (int o = 16; o; o >>= 1) {
                pmin = fminf(pmin, __shfl_xor_sync(0xFFFFFFFFu, pmin, o));
                nmax = fmaxf(nmax, __shfl_xor_sync(0xFFFFFFFFu, nmax, o));
            }
            if (lane == 0) {
                if (pmin < INFINITY)  atomicMinF(&g_pmin[bn + c], pmin);
                if (nmax > -INFINITY) atomicMaxF(&g_nmax[bn + c], nmax);
            }
        }
    }
}

// ---------------------------------------------------------------------------
// Kernel 3: hard-pair exp sums, warp-per-line over staged tile
// ---------------------------------------------------------------------------
__global__ __launch_bounds__(256) void sum_kernel(const int* __restrict__ labels) {
    extern __shared__ float st[];
    __shared__ int labA[128], labB[128];
    int by, bx;
    tri_decode(blockIdx.x, by, bx);
    const int bm = by * 128, bn = bx * 128;
    const bool diag = (bx == by);
    const int tid  = threadIdx.x;
    const int wid  = tid >> 5;
    const int lane = tid & 31;

    if (tid < 128) labA[tid] = labels[bm + tid];
    else           labB[tid - 128] = labels[bn + tid - 128];

    for (int t = tid; t < 128 * 32; t += 256) {
        const int r = t >> 5, c4 = (t & 31) * 4;
        float4 v = *(const float4*)(g_sim + (size_t)(bm + r) * NB + bn + c4);
        st[r * TLE + c4 + 0] = v.x; st[r * TLE + c4 + 1] = v.y;
        st[r * TLE + c4 + 2] = v.z; st[r * TLE + c4 + 3] = v.w;
    }
    __syncthreads();

    // rows: i = bm+r
    for (int k = 0; k < 16; k++) {
        const int r  = wid * 16 + k;
        const int i  = bm + r;
        const int li = labA[r];
        const float pmin = g_pmin[i], nmax = g_nmax[i];
        const float nthr = nmax - 0.45f;   // skipped terms < e^-22.5 * max term
        float psum = 0.0f, nsum = 0.0f;
#pragma unroll
        for (int q = 0; q < 4; q++) {
            const int c = lane + 32 * q;
            if (diag && c == r) continue;
            const float s = st[r * TLE + c];
            if (labB[c] == li) {
                if (s - C_MARGIN < nmax) psum += __expf(-C_ALPHA * (s - C_BASE));
            } else {
                if (s + C_MARGIN > pmin && s > nthr) nsum += __expf(C_BETA * (s - C_BASE));
            }
        }
#pragma unroll
        for (int o = 16; o; o >>= 1) {
            psum += __shfl_xor_sync(0xFFFFFFFFu, psum, o);
            nsum += __shfl_xor_sync(0xFFFFFFFFu, nsum, o);
        }
        if (lane == 0) {
            if (psum > 0.0f) atomicAdd(&g_psum[i], psum);
            if (nsum > 0.0f) atomicAdd(&g_nsum[i], nsum);
        }
    }
    // cols: i = bn+c (skip on diagonal)
    if (!diag) {
        for (int k = 0; k < 16; k++) {
            const int c  = wid * 16 + k;
            const int i  = bn + c;
            const int li = labB[c];
            const float pmin = g_pmin[i], nmax = g_nmax[i];
            const float nthr = nmax - 0.45f;
            float psum = 0.0f, nsum = 0.0f;
#pragma unroll
            for (int q = 0; q < 4; q++) {
                const int r = lane + 32 * q;
                const float s = st[r * TLE + c];
                if (labA[r] == li) {
                    if (s - C_MARGIN < nmax) psum += __expf(-C_ALPHA * (s - C_BASE));
                } else {
                    if (s + C_MARGIN > pmin && s > nthr) nsum += __expf(C_BETA * (s - C_BASE));
                }
            }
#pragma unroll
            for (int o = 16; o; o >>= 1) {
                psum += __shfl_xor_sync(0xFFFFFFFFu, psum, o);
                nsum += __shfl_xor_sync(0xFFFFFFFFu, nsum, o);
            }
            if (lane == 0) {
                if (psum > 0.0f) atomicAdd(&g_psum[i], psum);
                if (nsum > 0.0f) atomicAdd(&g_nsum[i], nsum);
            }
        }
    }
}

// ---------------------------------------------------------------------------
// Kernel 4: finalize (one CTA)
// ---------------------------------------------------------------------------
__global__ __launch_bounds__(1024) void final_kernel(float* __restrict__ out) {
    __shared__ float sbuf[32];
    __shared__ int   scnt[32];
    const int tid = threadIdx.x;
    float ls = 0.0f; int nv = 0;
    for (int i = tid; i < NB; i += 1024) {
        const float pmin = g_pmin[i], nmax = g_nmax[i];
        const float ps = g_psum[i], ns = g_nsum[i];
        if (pmin < INFINITY && nmax > -INFINITY && ps > 0.0f && ns > 0.0f) {
            ls += log1pf(ps) / C_ALPHA + log1pf(ns) / C_BETA;
            nv++;
        }
    }
#pragma unroll
    for (int o = 16; o; o >>= 1) {
        ls += __shfl_xor_sync(0xFFFFFFFFu, ls, o);
        nv += __shfl_xor_sync(0xFFFFFFFFu, nv, o);
    }
    if ((tid & 31) == 0) { sbuf[tid >> 5] = ls; scnt[tid >> 5] = nv; }
    __syncthreads();
    if (tid == 0) {
        float s = 0.0f; int n = 0;
#pragma unroll
        for (int k = 0; k < 32; k++) { s += sbuf[k]; n += scnt[k]; }
        out[0] = s / (float)(n > 1 ? n : 1);
    }
}

// ---------------------------------------------------------------------------
extern "C" void kernel_launch(void* const* d_in, const int* in_sizes, int n_in,
                              void* d_out, int out_size) {
    const float* E      = (const float*)d_in[0];
    const int*   labels = (const int*)d_in[1];
    float*       out    = (float*)d_out;

    cudaFuncSetAttribute(gemm_mma_kernel, cudaFuncAttributeMaxDynamicSharedMemorySize,
                         GEMM_SMEM);
    cudaFuncSetAttribute(extrema_kernel, cudaFuncAttributeMaxDynamicSharedMemorySize,
                         TILE_SMEM);
    cudaFuncSetAttribute(sum_kernel, cudaFuncAttributeMaxDynamicSharedMemorySize,
                         TILE_SMEM);

    split_kernel<<<NB * ND / 256, 256>>>(E);
    gemm_mma_kernel<<<NTRI, 256, GEMM_SMEM>>>();
    extrema_kernel<<<NTRI, 256, TILE_SMEM>>>(labels);
    sum_kernel<<<NTRI, 256, TILE_SMEM>>>(labels);
    final_kernel<<<1, 1024>>>(out);
}

// round 11
// speedup vs baseline: 1.5498x; 1.3658x over previous
#include <cuda_runtime.h>
#include <cuda_bf16.h>
#include <cstdint>
#include <math.h>

#define NB 8192
#define ND 128
#define C_ALPHA 2.0f
#define C_BETA 50.0f
#define C_BASE 0.5f
#define C_MARGIN 0.1f

// ---------------------------------------------------------------------------
// Scratch (allocation-free rule: __device__ globals)
// ---------------------------------------------------------------------------
__device__ float g_sim[(size_t)NB * NB];           // full matrix (both triangles)
__device__ __nv_bfloat16 g_Ehi[(size_t)NB * ND];
__device__ __nv_bfloat16 g_Elo[(size_t)NB * ND];
__device__ float g_loss_sum;
__device__ int   g_valid_cnt;
__device__ unsigned g_done;

__device__ __forceinline__ uint32_t smem_u32(const void* p) {
    uint32_t a;
    asm("{ .reg .u64 t; cvta.to.shared.u64 t, %1; cvt.u32.u64 %0, t; }" : "=r"(a) : "l"(p));
    return a;
}

#define LDMATRIX_X4(r0, r1, r2, r3, addr)                                      \
    asm volatile("ldmatrix.sync.aligned.m8n8.x4.shared.b16 {%0,%1,%2,%3}, [%4];" \
                 : "=r"(r0), "=r"(r1), "=r"(r2), "=r"(r3) : "r"(addr))
#define LDMATRIX_X2(r0, r1, addr)                                              \
    asm volatile("ldmatrix.sync.aligned.m8n8.x2.shared.b16 {%0,%1}, [%2];"     \
                 : "=r"(r0), "=r"(r1) : "r"(addr))
#define MMA16816(c, a, b)                                                      \
    asm volatile("mma.sync.aligned.m16n8k16.row.col.f32.bf16.bf16.f32 "        \
                 "{%0,%1,%2,%3}, {%4,%5,%6,%7}, {%8,%9}, {%0,%1,%2,%3};"       \
                 : "+f"((c)[0]), "+f"((c)[1]), "+f"((c)[2]), "+f"((c)[3])      \
                 : "r"((a)[0]), "r"((a)[1]), "r"((a)[2]), "r"((a)[3]),         \
                   "r"((b)[0]), "r"((b)[1]))
#define CP_ASYNC16(sa, gp)                                                     \
    asm volatile("cp.async.cg.shared.global [%0], [%1], 16;" :: "r"(sa), "l"(gp))
#define CP_COMMIT() asm volatile("cp.async.commit_group;")
#define CP_WAIT(n)  asm volatile("cp.async.wait_group %0;" :: "n"(n))

__device__ __forceinline__ void tri_decode(int t, int& by, int& bx) {
    int rem = t, y = 0;
    while (rem >= (NB / 128) - y) { rem -= (NB / 128) - y; y++; }
    by = y; bx = y + rem;
}

#define NTILE (NB / 128)
#define NTRI (NTILE * (NTILE + 1) / 2)    // 2080

// ---------------------------------------------------------------------------
// Kernel 0: split fp32 -> bf16 hi/lo, reset scalar accumulators
// ---------------------------------------------------------------------------
__global__ __launch_bounds__(256) void split_kernel(const float* __restrict__ E) {
    int i = blockIdx.x * 256 + threadIdx.x;
    if (i == 0) { g_loss_sum = 0.0f; g_valid_cnt = 0; g_done = 0u; }
    float x = E[i];
    __nv_bfloat16 h = __float2bfloat16(x);
    g_Ehi[i] = h;
    g_Elo[i] = __float2bfloat16(x - __bfloat162float(h));
}

// ---------------------------------------------------------------------------
// Kernel 1: triangular-grid GEMM, stores BOTH triangles (direct + transposed
// via SMEM stage). cp.async 2-group pipeline for operand tiles.
// ---------------------------------------------------------------------------
#define PAD 8
#define LDT (ND + PAD)
#define ROWB (LDT * 2)
#define OFF_AHI 0
#define OFF_ALO (OFF_AHI + 128 * ROWB)
#define OFF_BHI (OFF_ALO + 128 * ROWB)
#define OFF_BLO (OFF_BHI + 128 * ROWB)
#define GEMM_SMEM (OFF_BLO + 128 * ROWB)  // 139264
#define TLD 132                           // fp32 transpose-stage stride

__device__ __forceinline__ void gemm_pass(float (&acc)[4][4][4], uint32_t Ab, uint32_t Bb,
                                          int mbase, int nbase, int arow, int acol,
                                          int brow, int bcol) {
#pragma unroll
    for (int k0 = 0; k0 < ND; k0 += 16) {
        uint32_t a[4][4], b[4][2];
#pragma unroll
        for (int mi = 0; mi < 4; mi++) {
            uint32_t ad = Ab + ((mbase + mi * 16 + arow) * LDT + k0 + acol) * 2;
            LDMATRIX_X4(a[mi][0], a[mi][1], a[mi][2], a[mi][3], ad);
        }
#pragma unroll
        for (int ni = 0; ni < 4; ni++) {
            uint32_t bd = Bb + ((nbase + ni * 8 + brow) * LDT + k0 + bcol) * 2;
            LDMATRIX_X2(b[ni][0], b[ni][1], bd);
        }
#pragma unroll
        for (int mi = 0; mi < 4; mi++)
#pragma unroll
            for (int ni = 0; ni < 4; ni++)
                MMA16816(acc[mi][ni], a[mi], b[ni]);
    }
}

__global__ __launch_bounds__(256, 1) void gemm_mma_kernel() {
    int by, bx;
    tri_decode(blockIdx.x, by, bx);

    extern __shared__ char smem[];
    const uint32_t sbase = smem_u32(smem);
    const int tid  = threadIdx.x;
    const int wid  = tid >> 5;
    const int lane = tid & 31;
    const int bm = by * 128;
    const int bn = bx * 128;
    const bool diag = (bx == by);

    for (int t = tid; t < 2048; t += 256) {
        const int r = t >> 4;
        const int c = t & 15;
        const uint32_t so = (uint32_t)r * ROWB + c * 16;
        CP_ASYNC16(sbase + OFF_AHI + so, (const char*)(g_Ehi + (size_t)(bm + r) * ND) + c * 16);
        if (!diag)
            CP_ASYNC16(sbase + OFF_BHI + so, (const char*)(g_Ehi + (size_t)(bn + r) * ND) + c * 16);
    }
    CP_COMMIT();
    for (int t = tid; t < 2048; t += 256) {
        const int r = t >> 4;
        const int c = t & 15;
        const uint32_t so = (uint32_t)r * ROWB + c * 16;
        CP_ASYNC16(sbase + OFF_ALO + so, (const char*)(g_Elo + (size_t)(bm + r) * ND) + c * 16);
        if (!diag)
            CP_ASYNC16(sbase + OFF_BLO + so, (const char*)(g_Elo + (size_t)(bn + r) * ND) + c * 16);
    }
    CP_COMMIT();

    const int warp_m = wid >> 2;
    const int warp_n = wid & 3;
    const int mbase = warp_m * 64;
    const int nbase = warp_n * 32;
    const int arow = ((lane >> 3) & 1) * 8 + (lane & 7);
    const int acol = ((lane >> 4) & 1) * 8;
    const int brow = lane & 7;
    const int bcol = ((lane >> 3) & 1) * 8;

    float acc[4][4][4];
#pragma unroll
    for (int mi = 0; mi < 4; mi++)
#pragma unroll
        for (int ni = 0; ni < 4; ni++)
#pragma unroll
            for (int q = 0; q < 4; q++) acc[mi][ni][q] = 0.0f;

    const uint32_t aHi = sbase + OFF_AHI;
    const uint32_t aLo = sbase + OFF_ALO;
    const uint32_t bHi = diag ? aHi : sbase + OFF_BHI;
    const uint32_t bLo = diag ? aLo : sbase + OFF_BLO;

    CP_WAIT(1);
    __syncthreads();
    gemm_pass(acc, aHi, bHi, mbase, nbase, arow, acol, brow, bcol);   // hi*hi
    CP_WAIT(0);
    __syncthreads();
    gemm_pass(acc, aHi, bLo, mbase, nbase, arow, acol, brow, bcol);   // hi*lo
    gemm_pass(acc, aLo, bHi, mbase, nbase, arow, acol, brow, bcol);   // lo*hi

    // ---- direct store ----
    const int g   = lane >> 2;
    const int tig = lane & 3;
#pragma unroll
    for (int mi = 0; mi < 4; mi++) {
        const size_t row0 = (size_t)(bm + mbase + mi * 16 + g);
        const size_t row1 = row0 + 8;
#pragma unroll
        for (int ni = 0; ni < 4; ni++) {
            const int col = bn + nbase + ni * 8 + tig * 2;
            *(float2*)(g_sim + row0 * NB + col) = make_float2(acc[mi][ni][0], acc[mi][ni][1]);
            *(float2*)(g_sim + row1 * NB + col) = make_float2(acc[mi][ni][2], acc[mi][ni][3]);
        }
    }

    // ---- transposed store for off-diagonal tiles (SMEM stage) ----
    if (!diag) {
        __syncthreads();               // operand reads done; reuse smem
        float* st = (float*)smem;      // [128][TLD]
#pragma unroll
        for (int mi = 0; mi < 4; mi++) {
            const int r0 = mbase + mi * 16 + g;
#pragma unroll
            for (int ni = 0; ni < 4; ni++) {
                const int c0 = nbase + ni * 8 + tig * 2;
                st[(c0 + 0) * TLD + r0]     = acc[mi][ni][0];
                st[(c0 + 1) * TLD + r0]     = acc[mi][ni][1];
                st[(c0 + 0) * TLD + r0 + 8] = acc[mi][ni][2];
                st[(c0 + 1) * TLD + r0 + 8] = acc[mi][ni][3];
            }
        }
        __syncthreads();
        for (int t = tid; t < 128 * 32; t += 256) {
            const int r  = t >> 5;
            const int c4 = (t & 31) * 4;
            float4 v = *(float4*)(st + r * TLD + c4);
            *(float4*)(g_sim + (size_t)(bn + r) * NB + bm + c4) = v;
        }
    }
}

// ---------------------------------------------------------------------------
// Kernel 2: per-row mining + loss. 512 threads, 8 rows/CTA; row + labels in
// registers; warp-shuffle final reduces (no serial tails); per-CTA loss
// accumulation (2 atomics/CTA); last-CTA finalize.
// validity: anyPos<=>pmin<inf, anyNeg<=>nmax>-inf, hardPos<=>psum>0,
// hardNeg<=>nsum>0 (nmax elem is hard & above cutoff whenever any is).
// ---------------------------------------------------------------------------
#define RK_ROWS 8

__global__ __launch_bounds__(512, 2) void row_kernel(const int* __restrict__ labels,
                                                     float* __restrict__ out) {
    __shared__ float bufA[16], bufB[16];
    __shared__ float s_a, s_b;

    const int tid  = threadIdx.x;
    const int lane = tid & 31;
    const int wid  = tid >> 5;
    const int i0   = blockIdx.x * RK_ROWS;

    int4 lab[4];
#pragma unroll
    for (int q = 0; q < 4; q++) lab[q] = ((const int4*)labels)[q * 512 + tid];

    float loss_acc = 0.0f;
    int   cnt_acc  = 0;

    for (int r = 0; r < RK_ROWS; r++) {
        const int i  = i0 + r;
        const int li = __ldg(labels + i);

        float4 sv[4];
        const float4* row4 = (const float4*)(g_sim + (size_t)i * NB);
#pragma unroll
        for (int q = 0; q < 4; q++) sv[q] = row4[q * 512 + tid];

        // ---- pass 1: extrema ----
        float pmin = INFINITY, nmax = -INFINITY;
#pragma unroll
        for (int q = 0; q < 4; q++) {
            const int j0 = (q * 512 + tid) * 4;
            const float s[4] = {sv[q].x, sv[q].y, sv[q].z, sv[q].w};
            const int   l[4] = {lab[q].x, lab[q].y, lab[q].z, lab[q].w};
#pragma unroll
            for (int e = 0; e < 4; e++) {
                if (l[e] == li) { if (j0 + e != i) pmin = fminf(pmin, s[e]); }
                else nmax = fmaxf(nmax, s[e]);
            }
        }
#pragma unroll
        for (int o = 16; o; o >>= 1) {
            pmin = fminf(pmin, __shfl_xor_sync(0xFFFFFFFFu, pmin, o));
            nmax = fmaxf(nmax, __shfl_xor_sync(0xFFFFFFFFu, nmax, o));
        }
        if (lane == 0) { bufA[wid] = pmin; bufB[wid] = nmax; }
        __syncthreads();
        if (wid == 0) {
            float a = bufA[lane & 15];
            float m = bufB[lane & 15];
#pragma unroll
            for (int o = 8; o; o >>= 1) {
                a = fminf(a, __shfl_xor_sync(0xFFFFFFFFu, a, o));
                m = fmaxf(m, __shfl_xor_sync(0xFFFFFFFFu, m, o));
            }
            if (lane == 0) { s_a = a; s_b = m; }
        }
        __syncthreads();
        pmin = s_a;
        nmax = s_b;
        __syncthreads();          // protect bufA/bufB before pass-2 writes

        // ---- pass 2: hard-pair sums ----
        const float nthr = nmax - 0.45f;   // skipped terms < e^-22.5 * max term
        float psum = 0.0f, nsum = 0.0f;
#pragma unroll
        for (int q = 0; q < 4; q++) {
            const int j0 = (q * 512 + tid) * 4;
            const float s[4] = {sv[q].x, sv[q].y, sv[q].z, sv[q].w};
            const int   l[4] = {lab[q].x, lab[q].y, lab[q].z, lab[q].w};
#pragma unroll
            for (int e = 0; e < 4; e++) {
                const float sj = s[e];
                if (l[e] == li) {
                    if (j0 + e != i && sj - C_MARGIN < nmax)
                        psum += __expf(-C_ALPHA * (sj - C_BASE));
                } else {
                    if (sj + C_MARGIN > pmin && sj > nthr)
                        nsum += __expf(C_BETA * (sj - C_BASE));
                }
            }
        }
#pragma unroll
        for (int o = 16; o; o >>= 1) {
            psum += __shfl_xor_sync(0xFFFFFFFFu, psum, o);
            nsum += __shfl_xor_sync(0xFFFFFFFFu, nsum, o);
        }
        if (lane == 0) { bufA[wid] = psum; bufB[wid] = nsum; }
        __syncthreads();
        if (wid == 0) {
            float ps = bufA[lane & 15];
            float ns = bufB[lane & 15];
#pragma unroll
            for (int o = 8; o; o >>= 1) {
                ps += __shfl_xor_sync(0xFFFFFFFFu, ps, o);
                ns += __shfl_xor_sync(0xFFFFFFFFu, ns, o);
            }
            if (lane == 0) {
                if (pmin < INFINITY && nmax > -INFINITY && ps > 0.0f && ns > 0.0f) {
                    loss_acc += log1pf(ps) / C_ALPHA + log1pf(ns) / C_BETA;
                    cnt_acc++;
                }
            }
        }
        __syncthreads();          // bufs consumed before next row's writes
    }

    if (tid == 0) {
        if (cnt_acc > 0) {
            atomicAdd(&g_loss_sum, loss_acc);
            atomicAdd(&g_valid_cnt, cnt_acc);
        }
        __threadfence();
        const unsigned t = atomicAdd(&g_done, 1u);
        if (t == gridDim.x - 1) {
            const int nv = *((volatile int*)&g_valid_cnt);
            const float ls = *((volatile float*)&g_loss_sum);
            out[0] = ls / (float)(nv > 1 ? nv : 1);
        }
    }
}

// ---------------------------------------------------------------------------
extern "C" void kernel_launch(void* const* d_in, const int* in_sizes, int n_in,
                              void* d_out, int out_size) {
    const float* E      = (const float*)d_in[0];
    const int*   labels = (const int*)d_in[1];
    float*       out    = (float*)d_out;

    cudaFuncSetAttribute(gemm_mma_kernel, cudaFuncAttributeMaxDynamicSharedMemorySize,
                         GEMM_SMEM);

    split_kernel<<<NB * ND / 256, 256>>>(E);
    gemm_mma_kernel<<<NTRI, 256, GEMM_SMEM>>>();
    row_kernel<<<NB / RK_ROWS, 512>>>(labels, out);
}